// round 4
// baseline (speedup 1.0000x reference)
#include <cuda_runtime.h>

// PolyphaseDiff: resample_poly(x, up=3, down=2), 129-tap FIR.
// out[j] = sum_{c=0}^{42} a[c]*w[c],  w[c]=x[i0-42+c],  a[c]=3*h[pf+126-3c],
//   t=64+2j, pf=t%3, i0=t/3.
//
// f32x2 formulation: acc[r] packs (even-c partial, odd-c partial).
// Tap-pair k = (a[2k], a[2k+1]); window pair wp[i] = (w[2i], w[2i+1]).
// acc[r] += a2[k] * wp[k+r]. Pair 21 = (a[42], 0) absorbs the odd tail.
// Staggered window loads keep max live registers ~60 (no spills, unlike the
// full-preload version which ptxas spilled at 64 regs).

#define RR 8                 // outputs per thread
#define NPAIR 22             // 21 full tap pairs + zero-padded tail pair
#define THREADS 192          // 6 warps: warp w -> output-residue class w%3
#define NOUT_BLK 1536        // 3 classes * 64 threads/class * RR
#define TILE_W 1088          // x floats per block
#define TILE_ALLOC (TILE_W + TILE_W / 32 + 8)

typedef unsigned long long u64;

// bank swizzle for stride-16 lane pattern -> conflict-free
__device__ __forceinline__ int SW(int i) { return i + (i >> 5); }

#define FMA_X2(d, a, b, c) \
    asm("fma.rn.f32x2 %0, %1, %2, %3;" : "=l"(d) : "l"(a), "l"(b), "l"(c))
#define PACK_X2(d, lo, hi) \
    asm("mov.b64 %0, {%1, %2};" : "=l"(d) : "f"(lo), "f"(hi))
#define UNPACK_X2(lo, hi, s) \
    asm("mov.b64 {%0, %1}, %2;" : "=f"(lo), "=f"(hi) : "l"(s))

__global__ __launch_bounds__(THREADS, 2)
void poly_resample_kernel(const float* __restrict__ x,
                          const float* __restrict__ h,
                          float* __restrict__ out,
                          int N, int n_out)
{
    __shared__ float sh_x[TILE_ALLOC];
    __shared__ u64   sh_a2[3 * NPAIR];   // packed tap pairs per filter phase
    __shared__ float sh_out[NOUT_BLK];

    const int tid = threadIdx.x;
    const int Jb  = blockIdx.x * NOUT_BLK;
    const int IB  = (64 + 2 * Jb) / 3 - 42;

    // pack taps: pair k of phase pf = (3h[pf+126-6k], 3h[pf+123-6k]); k=21 -> (3h[pf], 0)
    if (tid < 3 * NPAIR) {
        int pf = tid / NPAIR, k = tid % NPAIR;
        float lo = 3.0f * h[pf + 126 - 6 * k];
        float hi = (k < 21) ? 3.0f * h[pf + 123 - 6 * k] : 0.0f;
        u64 d; PACK_X2(d, lo, hi);
        sh_a2[tid] = d;
    }

    // cooperative x tile, zero-padded edges, swizzled
    for (int m = tid; m < TILE_W; m += THREADS) {
        int g = IB + m;
        sh_x[SW(m)] = (g >= 0 && g < N) ? x[g] : 0.0f;
    }
    __syncthreads();

    const int wid  = tid >> 5;
    const int lane = tid & 31;
    const int p    = wid % 3;              // j mod 3 class (uniform per warp)
    const int pf   = (1 + 2 * p) % 3;      // filter phase: (64+2*j0) mod 3
    const int u    = (wid / 3) * 32 + lane;
    const int q0   = u * RR;
    const int j0   = Jb + 3 * q0 + p;
    const int i0   = (64 + 2 * j0) / 3;
    const int base = i0 - IB - 42;         // local index of w[0], >= 0

    // window pairs, loaded staggered to bound live range
    u64 wp[29];
    #pragma unroll
    for (int k = 0; k < 9; ++k) {
        float lo = sh_x[SW(base + 2 * k)];
        float hi = sh_x[SW(base + 2 * k + 1)];
        PACK_X2(wp[k], lo, hi);
    }

    u64 acc[RR];
    #pragma unroll
    for (int r = 0; r < RR; ++r) acc[r] = 0ull;

    const u64* a2 = sh_a2 + pf * NPAIR;
    #pragma unroll
    for (int k = 0; k < NPAIR; ++k) {
        if (k + 9 < 29) {                  // stagger: fetch pair needed at step k+2
            float lo = sh_x[SW(base + 2 * (k + 9))];
            float hi = sh_x[SW(base + 2 * (k + 9) + 1)];
            PACK_X2(wp[k + 9], lo, hi);
        }
        u64 ap = a2[k];                    // uniform per warp -> LDS.64 broadcast
        #pragma unroll
        for (int r = 0; r < RR; ++r)
            FMA_X2(acc[r], ap, wp[k + r], acc[r]);
    }

    // combine halves, stage (stride-3), coalesced store
    #pragma unroll
    for (int r = 0; r < RR; ++r) {
        float e, o; UNPACK_X2(e, o, acc[r]);
        sh_out[3 * (q0 + r) + p] = e + o;
    }
    __syncthreads();

    for (int m = tid; m < NOUT_BLK; m += THREADS) {
        int j = Jb + m;
        if (j < n_out) out[j] = sh_out[m];
    }
}

extern "C" void kernel_launch(void* const* d_in, const int* in_sizes, int n_in,
                              void* d_out, int out_size)
{
    const float* x = (const float*)d_in[0];
    const float* h = (const float*)d_in[1];
    float* out = (float*)d_out;

    const int N = in_sizes[0];
    const int n_out = out_size;
    const int grid = (n_out + NOUT_BLK - 1) / NOUT_BLK;   // 2048 for this shape

    poly_resample_kernel<<<grid, THREADS>>>(x, h, out, N, n_out);
}

// round 5
// speedup vs baseline: 1.1385x; 1.1385x over previous
#include <cuda_runtime.h>

// PolyphaseDiff: resample_poly(x, up=3, down=2), 129-tap FIR.
// out[j] = sum_c a_pf[c] * x[i0-42+c], t=64+2j, pf=t%3, i0=t/3, a_pf[c]=3h[pf+126-3c].
//
// Key structure (shape-specialized): T0=64+2*Jb == 1 (mod 3) for every block,
// so each class p in {0,1,2} has window start 16u + Dp with Dp={0,1,1}. The odd
// offset is absorbed into the tap pairing, giving ONE loop for all classes:
//     acc[r] += T[p][k] * tq[8u + r + k],  k=0..21   (fma.rn.f32x2)
// where tq[i]=(t[2i],t[2i+1]) is the x tile as u64 pairs and T[p][k] are
// pre-packed tap pairs (class 0: (a[2k],a[2k+1]) + zero tail; classes 1,2:
// (0,a[0]) head then (a[2k-1],a[2k])).
//
// Tile layout S(f)=f+(f>>3) (pad 1 pair per 8): lane base f=8u is 8-aligned so
// S(8u+m) = 9u + m + (m>>3) -> all loop loads are base + IMMEDIATE offset
// (zero ALU), and the 72B lane stride is bank-conflict-free for LDS.64.

#define RR 8                 // outputs per thread
#define NP 22                // tap pairs per class
#define THREADS 192          // 6 warps: warp w -> class w%3
#define NOUT_BLK 1536        // 3 * 64 * RR
#define TQ 536               // u64 pairs per tile (covers pair idx 0..532)
#define TQ_ALLOC (TQ + TQ / 8 + 2)

typedef unsigned long long u64;

#define FMA_X2(d, a, b, c) \
    asm("fma.rn.f32x2 %0, %1, %2, %3;" : "=l"(d) : "l"(a), "l"(b), "l"(c))
#define PACK_X2(d, lo, hi) \
    asm("mov.b64 %0, {%1, %2};" : "=l"(d) : "f"(lo), "f"(hi))
#define UNPACK_X2(lo, hi, s) \
    asm("mov.b64 {%0, %1}, %2;" : "=f"(lo), "=f"(hi) : "l"(s))

// padded pair index for cooperative stores (loads use the 9u+imm form)
__device__ __forceinline__ int SP(int i) { return i + (i >> 3); }

__global__ __launch_bounds__(THREADS, 6)
void poly_resample_kernel(const float* __restrict__ x,
                          const float* __restrict__ h,
                          float* __restrict__ out,
                          int N, int n_out)
{
    __shared__ u64 sh2[TQ_ALLOC];      // x tile pairs, padded layout
    __shared__ u64 sh_t[3 * NP];       // tap pairs per class

    const int tid = threadIdx.x;
    const int Jb  = blockIdx.x * NOUT_BLK;
    const int IB  = (64 + 2 * Jb) / 3 - 42;   // = 1024*blk - 21 (odd)

    // ---- pack taps: class c loop uses pf = (1+2p)%3 ----
    if (tid < 3 * NP) {
        int p = tid / NP, k = tid % NP;
        int pf = (1 + 2 * p) % 3;             // {1,0,2}
        float lo, hi;
        if (p == 0) {                         // pairs (a[2k], a[2k+1]), a[43]=0
            lo = 3.0f * h[127 - 6 * k];       // pf=1: a[2k]=3h[1+126-6k]
            hi = (k < 21) ? 3.0f * h[124 - 6 * k] : 0.0f;
        } else if (k == 0) {                  // head pair (0, a[0])
            lo = 0.0f;
            hi = 3.0f * h[pf + 126];
        } else {                              // (a[2k-1], a[2k])
            lo = 3.0f * h[pf + 129 - 6 * k];
            hi = 3.0f * h[pf + 126 - 6 * k];
        }
        u64 d; PACK_X2(d, lo, hi);
        sh_t[tid] = d;
    }

    // ---- cooperative x tile: pair i = (x[IB+2i], x[IB+2i+1]), zero-padded ----
    for (int i = tid; i < TQ; i += THREADS) {
        int g0 = IB + 2 * i, g1 = g0 + 1;
        float lo = (g0 >= 0 && g0 < N) ? x[g0] : 0.0f;
        float hi = (g1 >= 0 && g1 < N) ? x[g1] : 0.0f;
        u64 d; PACK_X2(d, lo, hi);
        sh2[SP(i)] = d;
    }
    __syncthreads();

    const int wid  = tid >> 5;
    const int lane = tid & 31;
    const int p    = wid % 3;                  // class = j mod 3 (uniform/warp)
    const int u    = (wid / 3) * 32 + lane;    // 0..63 within class
    const u64* __restrict__ wb = sh2 + 9 * u;  // padded base; offsets immediate
    const u64* __restrict__ T  = sh_t + p * NP;

    // staggered window: wp[m] = tq[8u+m] at wb[m + m/8]
    u64 wp[29];
    #pragma unroll
    for (int m = 0; m < 8; ++m)
        wp[m] = wb[m + (m >> 3)];

    u64 acc[RR];
    #pragma unroll
    for (int r = 0; r < RR; ++r) acc[r] = 0ull;

    #pragma unroll
    for (int k = 0; k < NP; ++k) {
        if (k + 8 < 29) {
            const int m = k + 8;
            wp[m] = wb[m + (m >> 3)];
        }
        const u64 tp = T[k];                   // uniform -> LDS.64 broadcast
        #pragma unroll
        for (int r = 0; r < RR; ++r)
            FMA_X2(acc[r], tp, wp[k + r], acc[r]);
    }

    // ---- epilogue: out[Jb + 3*(8u+r) + p] = lo(acc)+hi(acc) ----
    const int j0 = Jb + 24 * u + p;
    #pragma unroll
    for (int r = 0; r < RR; ++r) {
        float e, o; UNPACK_X2(e, o, acc[r]);
        int j = j0 + 3 * r;
        if (j < n_out) out[j] = e + o;
    }
}

extern "C" void kernel_launch(void* const* d_in, const int* in_sizes, int n_in,
                              void* d_out, int out_size)
{
    const float* x = (const float*)d_in[0];
    const float* h = (const float*)d_in[1];
    float* out = (float*)d_out;

    const int N = in_sizes[0];
    const int n_out = out_size;
    const int grid = (n_out + NOUT_BLK - 1) / NOUT_BLK;   // 2048 for this shape

    poly_resample_kernel<<<grid, THREADS>>>(x, h, out, N, n_out);
}

// round 6
// speedup vs baseline: 1.1661x; 1.0242x over previous
#include <cuda_runtime.h>

// PolyphaseDiff: resample_poly(x, up=3, down=2), 129-tap FIR.
// out[j] = sum_c a_pf[c] * x[i0-42+c], t=64+2j, pf=t%3, i0=t/3, a_pf[c]=3h[pf+126-3c].
//
// One-loop formulation (shape-specialized): T0=64+2*Jb == 1 (mod 3) for every
// block, so class p's window start is 16u + Dp, Dp={0,1,1}; the odd offset is
// absorbed into the tap pairing, giving a single loop for all classes:
//     acc[r] += T[p][k] * tq[8u + r + k],  k=0..21   (fma.rn.f32x2)
// tq[i]=(x[IB+2i],x[IB+2i+1]) as u64 pairs; T[p][k] pre-packed per class.
//
// Tile layout pad-1-per-8: lane base f=8u is 8-aligned so the padded address is
// 9u + m + (m>>3) -> all loop loads are base + IMMEDIATE offset (no ALU), and
// the 72B lane stride is bank-conflict-free for LDS.64.
//
// R6 change: software-pipeline depth. Window pair wp[k+14] is fetched at step k
// and first consumed at step k+7 (~60 instructions later), fully covering the
// 29-cycle LDS latency (R5 fetched only 1 step ahead -> per-iteration stall).

#define RR 8                 // outputs per thread
#define NP 22                // tap pairs per class
#define LOOKAHEAD 14         // window pairs resident ahead of consumption
#define THREADS 192          // 6 warps: warp w -> class w%3
#define NOUT_BLK 1536        // 3 * 64 * RR
#define TQ 536               // u64 pairs per tile
#define TQ_ALLOC (TQ + TQ / 8 + 2)

typedef unsigned long long u64;

#define FMA_X2(d, a, b, c) \
    asm("fma.rn.f32x2 %0, %1, %2, %3;" : "=l"(d) : "l"(a), "l"(b), "l"(c))
#define PACK_X2(d, lo, hi) \
    asm("mov.b64 %0, {%1, %2};" : "=l"(d) : "f"(lo), "f"(hi))
#define UNPACK_X2(lo, hi, s) \
    asm("mov.b64 {%0, %1}, %2;" : "=f"(lo), "=f"(hi) : "l"(s))

__device__ __forceinline__ int SP(int i) { return i + (i >> 3); }

__global__ __launch_bounds__(THREADS, 5)
void poly_resample_kernel(const float* __restrict__ x,
                          const float* __restrict__ h,
                          float* __restrict__ out,
                          int N, int n_out)
{
    __shared__ u64 sh2[TQ_ALLOC];      // x tile pairs, padded layout
    __shared__ u64 sh_t[3 * NP];       // tap pairs per class

    const int tid = threadIdx.x;
    const int Jb  = blockIdx.x * NOUT_BLK;
    const int IB  = (64 + 2 * Jb) / 3 - 42;

    // ---- pack taps: class p uses filter phase pf = (1+2p)%3 ----
    if (tid < 3 * NP) {
        int p = tid / NP, k = tid % NP;
        int pf = (1 + 2 * p) % 3;             // {1,0,2}
        float lo, hi;
        if (p == 0) {                         // (a[2k], a[2k+1]), zero tail
            lo = 3.0f * h[127 - 6 * k];
            hi = (k < 21) ? 3.0f * h[124 - 6 * k] : 0.0f;
        } else if (k == 0) {                  // head pair (0, a[0])
            lo = 0.0f;
            hi = 3.0f * h[pf + 126];
        } else {                              // (a[2k-1], a[2k])
            lo = 3.0f * h[pf + 129 - 6 * k];
            hi = 3.0f * h[pf + 126 - 6 * k];
        }
        u64 d; PACK_X2(d, lo, hi);
        sh_t[tid] = d;
    }

    // ---- cooperative x tile: pair i = (x[IB+2i], x[IB+2i+1]), zero-padded ----
    for (int i = tid; i < TQ; i += THREADS) {
        int g0 = IB + 2 * i, g1 = g0 + 1;
        float lo = (g0 >= 0 && g0 < N) ? x[g0] : 0.0f;
        float hi = (g1 >= 0 && g1 < N) ? x[g1] : 0.0f;
        u64 d; PACK_X2(d, lo, hi);
        sh2[SP(i)] = d;
    }
    __syncthreads();

    const int wid  = tid >> 5;
    const int lane = tid & 31;
    const int p    = wid % 3;                  // class = j mod 3 (uniform/warp)
    const int u    = (wid / 3) * 32 + lane;    // 0..63 within class
    const u64* __restrict__ wb = sh2 + 9 * u;  // padded base; offsets immediate
    const u64* __restrict__ T  = sh_t + p * NP;

    // deep-pipelined window: preload LOOKAHEAD pairs
    u64 wp[29];
    #pragma unroll
    for (int m = 0; m < LOOKAHEAD; ++m)
        wp[m] = wb[m + (m >> 3)];

    u64 acc[RR];
    #pragma unroll
    for (int r = 0; r < RR; ++r) acc[r] = 0ull;

    #pragma unroll
    for (int k = 0; k < NP; ++k) {
        if (k + LOOKAHEAD < 29) {              // fetched 7 steps before first use
            const int m = k + LOOKAHEAD;
            wp[m] = wb[m + (m >> 3)];
        }
        const u64 tp = T[k];                   // uniform -> LDS.64 broadcast
        #pragma unroll
        for (int r = 0; r < RR; ++r)
            FMA_X2(acc[r], tp, wp[k + r], acc[r]);
    }

    // ---- epilogue: out[Jb + 3*(8u+r) + p] = lo(acc)+hi(acc) ----
    const int j0 = Jb + 24 * u + p;
    #pragma unroll
    for (int r = 0; r < RR; ++r) {
        float e, o; UNPACK_X2(e, o, acc[r]);
        int j = j0 + 3 * r;
        if (j < n_out) out[j] = e + o;
    }
}

extern "C" void kernel_launch(void* const* d_in, const int* in_sizes, int n_in,
                              void* d_out, int out_size)
{
    const float* x = (const float*)d_in[0];
    const float* h = (const float*)d_in[1];
    float* out = (float*)d_out;

    const int N = in_sizes[0];
    const int n_out = out_size;
    const int grid = (n_out + NOUT_BLK - 1) / NOUT_BLK;   // 2048 for this shape

    poly_resample_kernel<<<grid, THREADS>>>(x, h, out, N, n_out);
}

// round 7
// speedup vs baseline: 1.2390x; 1.0625x over previous
#include <cuda_runtime.h>

// PolyphaseDiff: resample_poly(x, up=3, down=2), 129-tap FIR.
// out[j] = sum_c a_pf[c] * x[i0-42+c], t=64+2j, pf=t%3, i0=t/3, a_pf[c]=3h[pf+126-3c].
//
// Compute core (validated R5/R6): one f32x2 loop for all 3 output classes,
//   acc[r] += T[p][k] * tq[8u + r + k], k=0..21,
// tile held as u64 pairs in padded smem (9u + immediate addressing, LDS.64
// conflict-free), taps phase-folded per class.
//
// R7: the kernel is L1tex-wavefront + load-latency bound, so
//  (a) outputs staged in shared (stride-3 STS is conflict-free) then stored
//      coalesced  -> replaces 96 strided-STG wavefronts/warp with ~16;
//  (b) each block processes TPB=4 tiles with register-prefetch double
//      buffering -> tile-load DRAM latency exposed once per CTA, not per tile.

#define RR 8                 // outputs per thread
#define NP 22                // tap pairs per class
#define LOOKAHEAD 14         // window pairs resident ahead of consumption
#define THREADS 192          // 6 warps: warp w -> class w%3
#define NOUT_BLK 1536        // outputs per tile = 3 * 64 * RR
#define TPB 4                // tiles per block
#define TQ 536               // u64 pairs per tile
#define TQ_ALLOC (TQ + TQ / 8 + 2)

typedef unsigned long long u64;

#define FMA_X2(d, a, b, c) \
    asm("fma.rn.f32x2 %0, %1, %2, %3;" : "=l"(d) : "l"(a), "l"(b), "l"(c))
#define PACK_X2(d, lo, hi) \
    asm("mov.b64 %0, {%1, %2};" : "=l"(d) : "f"(lo), "f"(hi))
#define UNPACK_X2(lo, hi, s) \
    asm("mov.b64 {%0, %1}, %2;" : "=f"(lo), "=f"(hi) : "l"(s))

__device__ __forceinline__ int SP(int i) { return i + (i >> 3); }

__global__ __launch_bounds__(THREADS, 5)
void poly_resample_kernel(const float* __restrict__ x,
                          const float* __restrict__ h,
                          float* __restrict__ out,
                          int N, int n_out)
{
    __shared__ u64   sh2[2][TQ_ALLOC];   // double-buffered x tile pairs
    __shared__ u64   sh_t[3 * NP];       // tap pairs per class
    __shared__ float sh_out[NOUT_BLK];   // output staging

    const int tid = threadIdx.x;

    // ---- pack taps: class p uses filter phase pf = (1+2p)%3 ----
    if (tid < 3 * NP) {
        int p = tid / NP, k = tid % NP;
        int pf = (1 + 2 * p) % 3;             // {1,0,2}
        float lo, hi;
        if (p == 0) {                         // (a[2k], a[2k+1]), zero tail
            lo = 3.0f * h[127 - 6 * k];
            hi = (k < 21) ? 3.0f * h[124 - 6 * k] : 0.0f;
        } else if (k == 0) {                  // head pair (0, a[0])
            lo = 0.0f;
            hi = 3.0f * h[pf + 126];
        } else {                              // (a[2k-1], a[2k])
            lo = 3.0f * h[pf + 129 - 6 * k];
            hi = 3.0f * h[pf + 126 - 6 * k];
        }
        u64 d; PACK_X2(d, lo, hi);
        sh_t[tid] = d;
    }

    const int t0 = blockIdx.x * TPB;          // first tile of this block

    // ---- load first tile into buffer 0 ----
    {
        const int IB = 1024 * t0 - 21;
        for (int i = tid; i < TQ; i += THREADS) {
            int g0 = IB + 2 * i, g1 = g0 + 1;
            float lo = (g0 >= 0 && g0 < N) ? x[g0] : 0.0f;
            float hi = (g1 >= 0 && g1 < N) ? x[g1] : 0.0f;
            u64 d; PACK_X2(d, lo, hi);
            sh2[0][SP(i)] = d;
        }
    }
    __syncthreads();

    const int wid  = tid >> 5;
    const int lane = tid & 31;
    const int p    = wid % 3;                 // class = j mod 3 (uniform/warp)
    const int u    = (wid / 3) * 32 + lane;   // 0..63 within class
    const u64* __restrict__ T = sh_t + p * NP;

    int cur = 0;
    for (int t = 0; t < TPB; ++t) {
        const int tt = t0 + t;
        const bool hasnext = (t + 1 < TPB);

        // prefetch next tile into registers (issued before compute)
        u64 pf3[3];
        if (hasnext) {
            const int IBn = 1024 * (tt + 1) - 21;
            #pragma unroll
            for (int q = 0; q < 3; ++q) {
                int i = tid + q * THREADS;
                float lo = 0.0f, hi = 0.0f;
                if (i < TQ) {
                    int g0 = IBn + 2 * i, g1 = g0 + 1;
                    if (g0 >= 0 && g0 < N) lo = x[g0];
                    if (g1 >= 0 && g1 < N) hi = x[g1];
                }
                PACK_X2(pf3[q], lo, hi);
            }
        }

        // ---- compute tile tt from sh2[cur] ----
        const u64* __restrict__ wb = &sh2[cur][0] + 9 * u;

        u64 wp[29];
        #pragma unroll
        for (int m = 0; m < LOOKAHEAD; ++m)
            wp[m] = wb[m + (m >> 3)];

        u64 acc[RR];
        #pragma unroll
        for (int r = 0; r < RR; ++r) acc[r] = 0ull;

        #pragma unroll
        for (int k = 0; k < NP; ++k) {
            if (k + LOOKAHEAD < 29) {
                const int m = k + LOOKAHEAD;
                wp[m] = wb[m + (m >> 3)];
            }
            const u64 tp = T[k];               // uniform -> LDS.64 broadcast
            #pragma unroll
            for (int r = 0; r < RR; ++r)
                FMA_X2(acc[r], tp, wp[k + r], acc[r]);
        }

        // stage outputs (stride-3 STS: gcd(3,32)=1 -> conflict-free)
        const int q0 = u * RR;
        #pragma unroll
        for (int r = 0; r < RR; ++r) {
            float e, o; UNPACK_X2(e, o, acc[r]);
            sh_out[3 * (q0 + r) + p] = e + o;
        }
        __syncthreads();

        // coalesced global store
        const int Jb = tt * NOUT_BLK;
        for (int m = tid; m < NOUT_BLK; m += THREADS) {
            int j = Jb + m;
            if (j < n_out) out[j] = sh_out[m];
        }

        // commit prefetched tile into the other buffer
        if (hasnext) {
            #pragma unroll
            for (int q = 0; q < 3; ++q) {
                int i = tid + q * THREADS;
                if (i < TQ) sh2[cur ^ 1][SP(i)] = pf3[q];
            }
        }
        __syncthreads();
        cur ^= 1;
    }
}

extern "C" void kernel_launch(void* const* d_in, const int* in_sizes, int n_in,
                              void* d_out, int out_size)
{
    const float* x = (const float*)d_in[0];
    const float* h = (const float*)d_in[1];
    float* out = (float*)d_out;

    const int N = in_sizes[0];
    const int n_out = out_size;
    const int total_tiles = (n_out + NOUT_BLK - 1) / NOUT_BLK;   // 2048
    const int grid = (total_tiles + TPB - 1) / TPB;              // 512

    poly_resample_kernel<<<grid, THREADS>>>(x, h, out, N, n_out);
}

// round 8
// speedup vs baseline: 1.4310x; 1.1550x over previous
#include <cuda_runtime.h>

// PolyphaseDiff: resample_poly(x, up=3, down=2), 129-tap FIR.
// out[j] = sum_c a_pf[c] * x[i0-42+c], t=64+2j, pf=t%3, i0=t/3, a_pf[c]=3h[pf+126-3c].
//
// Compute core (validated R5-R7): one f32x2 loop for all 3 output classes,
//   acc[r] += T[p][k] * tq[8u + r + k], k=0..21,
// tile held as u64 pairs in padded smem (9u + immediate addressing, LDS.64
// conflict-free), taps phase-folded per class. Outputs staged in shared
// (stride-3 STS conflict-free) then stored coalesced. Next tile prefetched
// into registers during compute (double-buffered smem).
//
// R8: TPB=3 -> grid=683 CTAs = ONE wave at the 5-CTA/SM register cap
// (vs TPB=4/grid=512 which left the chip at 3.5 CTAs/SM, occ 28.7%).

#define RR 8                 // outputs per thread
#define NP 22                // tap pairs per class
#define LOOKAHEAD 14         // window pairs resident ahead of consumption
#define THREADS 192          // 6 warps: warp w -> class w%3
#define NOUT_BLK 1536        // outputs per tile = 3 * 64 * RR
#define TPB 3                // tiles per block (single-wave grid)
#define TQ 536               // u64 pairs per tile
#define TQ_ALLOC (TQ + TQ / 8 + 2)

typedef unsigned long long u64;

#define FMA_X2(d, a, b, c) \
    asm("fma.rn.f32x2 %0, %1, %2, %3;" : "=l"(d) : "l"(a), "l"(b), "l"(c))
#define PACK_X2(d, lo, hi) \
    asm("mov.b64 %0, {%1, %2};" : "=l"(d) : "f"(lo), "f"(hi))
#define UNPACK_X2(lo, hi, s) \
    asm("mov.b64 {%0, %1}, %2;" : "=f"(lo), "=f"(hi) : "l"(s))

__device__ __forceinline__ int SP(int i) { return i + (i >> 3); }

__global__ __launch_bounds__(THREADS, 5)
void poly_resample_kernel(const float* __restrict__ x,
                          const float* __restrict__ h,
                          float* __restrict__ out,
                          int N, int n_out, int n_tiles)
{
    __shared__ u64   sh2[2][TQ_ALLOC];   // double-buffered x tile pairs
    __shared__ u64   sh_t[3 * NP];       // tap pairs per class
    __shared__ float sh_out[NOUT_BLK];   // output staging

    const int tid = threadIdx.x;

    // ---- pack taps: class p uses filter phase pf = (1+2p)%3 ----
    if (tid < 3 * NP) {
        int p = tid / NP, k = tid % NP;
        int pf = (1 + 2 * p) % 3;             // {1,0,2}
        float lo, hi;
        if (p == 0) {                         // (a[2k], a[2k+1]), zero tail
            lo = 3.0f * h[127 - 6 * k];
            hi = (k < 21) ? 3.0f * h[124 - 6 * k] : 0.0f;
        } else if (k == 0) {                  // head pair (0, a[0])
            lo = 0.0f;
            hi = 3.0f * h[pf + 126];
        } else {                              // (a[2k-1], a[2k])
            lo = 3.0f * h[pf + 129 - 6 * k];
            hi = 3.0f * h[pf + 126 - 6 * k];
        }
        u64 d; PACK_X2(d, lo, hi);
        sh_t[tid] = d;
    }

    const int t0 = blockIdx.x * TPB;          // first tile of this block
    const int ntloc = min(TPB, n_tiles - t0); // tiles this block actually owns

    // ---- load first tile into buffer 0 ----
    {
        const int IB = 1024 * t0 - 21;
        for (int i = tid; i < TQ; i += THREADS) {
            int g0 = IB + 2 * i, g1 = g0 + 1;
            float lo = (g0 >= 0 && g0 < N) ? x[g0] : 0.0f;
            float hi = (g1 >= 0 && g1 < N) ? x[g1] : 0.0f;
            u64 d; PACK_X2(d, lo, hi);
            sh2[0][SP(i)] = d;
        }
    }
    __syncthreads();

    const int wid  = tid >> 5;
    const int lane = tid & 31;
    const int p    = wid % 3;                 // class = j mod 3 (uniform/warp)
    const int u    = (wid / 3) * 32 + lane;   // 0..63 within class
    const u64* __restrict__ T = sh_t + p * NP;

    int cur = 0;
    for (int t = 0; t < ntloc; ++t) {
        const int tt = t0 + t;
        const bool hasnext = (t + 1 < ntloc);

        // prefetch next tile into registers (issued before compute)
        u64 pf3[3];
        if (hasnext) {
            const int IBn = 1024 * (tt + 1) - 21;
            #pragma unroll
            for (int q = 0; q < 3; ++q) {
                int i = tid + q * THREADS;
                float lo = 0.0f, hi = 0.0f;
                if (i < TQ) {
                    int g0 = IBn + 2 * i, g1 = g0 + 1;
                    if (g0 >= 0 && g0 < N) lo = x[g0];
                    if (g1 >= 0 && g1 < N) hi = x[g1];
                }
                PACK_X2(pf3[q], lo, hi);
            }
        }

        // ---- compute tile tt from sh2[cur] ----
        const u64* __restrict__ wb = &sh2[cur][0] + 9 * u;

        u64 wp[29];
        #pragma unroll
        for (int m = 0; m < LOOKAHEAD; ++m)
            wp[m] = wb[m + (m >> 3)];

        u64 acc[RR];
        #pragma unroll
        for (int r = 0; r < RR; ++r) acc[r] = 0ull;

        #pragma unroll
        for (int k = 0; k < NP; ++k) {
            if (k + LOOKAHEAD < 29) {
                const int m = k + LOOKAHEAD;
                wp[m] = wb[m + (m >> 3)];
            }
            const u64 tp = T[k];               // uniform -> LDS.64 broadcast
            #pragma unroll
            for (int r = 0; r < RR; ++r)
                FMA_X2(acc[r], tp, wp[k + r], acc[r]);
        }

        // stage outputs (stride-3 STS: gcd(3,32)=1 -> conflict-free)
        const int q0 = u * RR;
        #pragma unroll
        for (int r = 0; r < RR; ++r) {
            float e, o; UNPACK_X2(e, o, acc[r]);
            sh_out[3 * (q0 + r) + p] = e + o;
        }
        __syncthreads();

        // coalesced global store
        const int Jb = tt * NOUT_BLK;
        for (int m = tid; m < NOUT_BLK; m += THREADS) {
            int j = Jb + m;
            if (j < n_out) out[j] = sh_out[m];
        }

        // commit prefetched tile into the other buffer
        if (hasnext) {
            #pragma unroll
            for (int q = 0; q < 3; ++q) {
                int i = tid + q * THREADS;
                if (i < TQ) sh2[cur ^ 1][SP(i)] = pf3[q];
            }
        }
        __syncthreads();
        cur ^= 1;
    }
}

extern "C" void kernel_launch(void* const* d_in, const int* in_sizes, int n_in,
                              void* d_out, int out_size)
{
    const float* x = (const float*)d_in[0];
    const float* h = (const float*)d_in[1];
    float* out = (float*)d_out;

    const int N = in_sizes[0];
    const int n_out = out_size;
    const int n_tiles = (n_out + NOUT_BLK - 1) / NOUT_BLK;       // 2048
    const int grid = (n_tiles + TPB - 1) / TPB;                  // 683

    poly_resample_kernel<<<grid, THREADS>>>(x, h, out, N, n_out, n_tiles);
}

// round 10
// speedup vs baseline: 1.4526x; 1.0151x over previous
#include <cuda_runtime.h>

// PolyphaseDiff: resample_poly(x, up=3, down=2), 129-tap FIR.
// out[j] = sum_c a_pf[c] * x[i0-42+c], t=64+2j, pf=t%3, i0=t/3, a_pf[c]=3h[pf+126-3c].
//
// Compute core (validated R5-R8): one f32x2 loop for all 3 output classes,
//   acc[r] += T[p][k] * tq[8u + r + k], k=0..21,
// tile held as u64 pairs in padded smem (9u + immediate addressing, LDS.64
// conflict-free), taps phase-folded per class. Outputs staged in shared
// (stride-3 STS conflict-free) then stored coalesced (float4).
//
// R10 = R9 + alignment fix: sh_out must be 16B-aligned for the float4
// (LDS.128/STG.128) store path — plain __shared__ float[] landed on an
// 8B boundary and trapped (misaligned address).

#define RR 8                 // outputs per thread
#define NP 22                // tap pairs per class
#define LOOKAHEAD 8          // window pairs preloaded (1-step stagger)
#define THREADS 192          // 6 warps: warp w -> class w%3
#define NOUT_BLK 1536        // outputs per tile = 3 * 64 * RR
#define TQ 536               // u64 pairs per tile
#define TQ_ALLOC (TQ + TQ / 8 + 2)

typedef unsigned long long u64;

#define FMA_X2(d, a, b, c) \
    asm("fma.rn.f32x2 %0, %1, %2, %3;" : "=l"(d) : "l"(a), "l"(b), "l"(c))
#define PACK_X2(d, lo, hi) \
    asm("mov.b64 %0, {%1, %2};" : "=l"(d) : "f"(lo), "f"(hi))
#define UNPACK_X2(lo, hi, s) \
    asm("mov.b64 {%0, %1}, %2;" : "=f"(lo), "=f"(hi) : "l"(s))

__device__ __forceinline__ int SP(int i) { return i + (i >> 3); }

__global__ __launch_bounds__(THREADS, 7)
void poly_resample_kernel(const float* __restrict__ x,
                          const float* __restrict__ h,
                          float* __restrict__ out,
                          int N, int n_out)
{
    __shared__ __align__(16) u64   sh2[TQ_ALLOC];      // x tile pairs, padded
    __shared__ __align__(16) u64   sh_t[3 * NP];       // tap pairs per class
    __shared__ __align__(16) float sh_out[NOUT_BLK];   // output staging

    const int tid = threadIdx.x;
    const int tt  = blockIdx.x;          // tile index
    const int Jb  = tt * NOUT_BLK;
    const int IB  = 1024 * tt - 21;

    // ---- pack taps: class p uses filter phase pf = (1+2p)%3 ----
    if (tid < 3 * NP) {
        int p = tid / NP, k = tid % NP;
        int pf = (1 + 2 * p) % 3;             // {1,0,2}
        float lo, hi;
        if (p == 0) {                         // (a[2k], a[2k+1]), zero tail
            lo = 3.0f * h[127 - 6 * k];
            hi = (k < 21) ? 3.0f * h[124 - 6 * k] : 0.0f;
        } else if (k == 0) {                  // head pair (0, a[0])
            lo = 0.0f;
            hi = 3.0f * h[pf + 126];
        } else {                              // (a[2k-1], a[2k])
            lo = 3.0f * h[pf + 129 - 6 * k];
            hi = 3.0f * h[pf + 126 - 6 * k];
        }
        u64 d; PACK_X2(d, lo, hi);
        sh_t[tid] = d;
    }

    // ---- cooperative x tile: pair i = (x[IB+2i], x[IB+2i+1]), zero-padded ----
    for (int i = tid; i < TQ; i += THREADS) {
        int g0 = IB + 2 * i, g1 = g0 + 1;
        float lo = (g0 >= 0 && g0 < N) ? x[g0] : 0.0f;
        float hi = (g1 >= 0 && g1 < N) ? x[g1] : 0.0f;
        u64 d; PACK_X2(d, lo, hi);
        sh2[SP(i)] = d;
    }
    __syncthreads();

    const int wid  = tid >> 5;
    const int lane = tid & 31;
    const int p    = wid % 3;                 // class = j mod 3 (uniform/warp)
    const int u    = (wid / 3) * 32 + lane;   // 0..63 within class
    const u64* __restrict__ T  = sh_t + p * NP;
    const u64* __restrict__ wb = sh2 + 9 * u; // padded base; offsets immediate

    u64 wp[29];
    #pragma unroll
    for (int m = 0; m < LOOKAHEAD; ++m)
        wp[m] = wb[m + (m >> 3)];

    u64 acc[RR];
    #pragma unroll
    for (int r = 0; r < RR; ++r) acc[r] = 0ull;

    #pragma unroll
    for (int k = 0; k < NP; ++k) {
        if (k + LOOKAHEAD < 29) {
            const int m = k + LOOKAHEAD;
            wp[m] = wb[m + (m >> 3)];
        }
        const u64 tp = T[k];                   // uniform -> LDS.64 broadcast
        #pragma unroll
        for (int r = 0; r < RR; ++r)
            FMA_X2(acc[r], tp, wp[k + r], acc[r]);
    }

    // stage outputs (stride-3 STS: gcd(3,32)=1 -> conflict-free)
    const int q0 = u * RR;
    #pragma unroll
    for (int r = 0; r < RR; ++r) {
        float e, o; UNPACK_X2(e, o, acc[r]);
        sh_out[3 * (q0 + r) + p] = e + o;
    }
    __syncthreads();

    // coalesced global store, vectorized (tiles exactly cover n_out normally)
    if (Jb + NOUT_BLK <= n_out) {
        const float4* __restrict__ s4 = (const float4*)sh_out;
        float4* __restrict__ o4 = (float4*)(out + Jb);
        #pragma unroll
        for (int q = 0; q < NOUT_BLK / 4 / THREADS; ++q)   // 2 iterations
            o4[tid + q * THREADS] = s4[tid + q * THREADS];
    } else {
        for (int m = tid; m < NOUT_BLK; m += THREADS) {
            int j = Jb + m;
            if (j < n_out) out[j] = sh_out[m];
        }
    }
}

extern "C" void kernel_launch(void* const* d_in, const int* in_sizes, int n_in,
                              void* d_out, int out_size)
{
    const float* x = (const float*)d_in[0];
    const float* h = (const float*)d_in[1];
    float* out = (float*)d_out;

    const int N = in_sizes[0];
    const int n_out = out_size;
    const int grid = (n_out + NOUT_BLK - 1) / NOUT_BLK;   // 2048

    poly_resample_kernel<<<grid, THREADS>>>(x, h, out, N, n_out);
}

// round 11
// speedup vs baseline: 1.4557x; 1.0022x over previous
#include <cuda_runtime.h>

// PolyphaseDiff: resample_poly(x, up=3, down=2), 129-tap FIR.
// out[j] = sum_c a_pf[c] * x[i0-42+c], t=64+2j, pf=t%3, i0=t/3, a_pf[c]=3h[pf+126-3c].
//
// Compute core (validated R5-R10): one f32x2 loop for all 3 output classes,
//   acc[r] += T[p][k] * tq[8u + r + k], k=0..21,
// tile held as u64 pairs in padded smem (9u + immediate addressing, LDS.64
// conflict-free), taps phase-folded per class. Outputs staged in shared
// (stride-3 STS conflict-free) then stored coalesced via float4 (16B-aligned).
//
// R11: combine the two independently-validated wins that were never co-resident:
//   - R10's occupancy (TPB small, 7-CTA/SM cap, lean 40-reg body)
//   - R8's register-prefetch + double-buffered smem (hides tile LDG latency
//     inside the CTA instead of exposing it at the post-load barrier)
// TPB=2, grid=1024 = 6.9 CTAs/SM at cap 7 -> single wave, R10 occupancy,
// with the 2nd tile's LDG issued before the 1st tile's compute.

#define RR 8                 // outputs per thread
#define NP 22                // tap pairs per class
#define LOOKAHEAD 8          // window pairs preloaded (1-step stagger)
#define THREADS 192          // 6 warps: warp w -> class w%3
#define NOUT_BLK 1536        // outputs per tile = 3 * 64 * RR
#define TPB 2                // tiles per block
#define TQ 536               // u64 pairs per tile
#define TQ_ALLOC (TQ + TQ / 8 + 2)

typedef unsigned long long u64;

#define FMA_X2(d, a, b, c) \
    asm("fma.rn.f32x2 %0, %1, %2, %3;" : "=l"(d) : "l"(a), "l"(b), "l"(c))
#define PACK_X2(d, lo, hi) \
    asm("mov.b64 %0, {%1, %2};" : "=l"(d) : "f"(lo), "f"(hi))
#define UNPACK_X2(lo, hi, s) \
    asm("mov.b64 {%0, %1}, %2;" : "=f"(lo), "=f"(hi) : "l"(s))

__device__ __forceinline__ int SP(int i) { return i + (i >> 3); }

__global__ __launch_bounds__(THREADS, 7)
void poly_resample_kernel(const float* __restrict__ x,
                          const float* __restrict__ h,
                          float* __restrict__ out,
                          int N, int n_out, int n_tiles)
{
    __shared__ __align__(16) u64   sh2[2][TQ_ALLOC];   // double-buffered tile
    __shared__ __align__(16) u64   sh_t[3 * NP];       // tap pairs per class
    __shared__ __align__(16) float sh_out[NOUT_BLK];   // output staging

    const int tid = threadIdx.x;

    // ---- pack taps: class p uses filter phase pf = (1+2p)%3 ----
    if (tid < 3 * NP) {
        int p = tid / NP, k = tid % NP;
        int pf = (1 + 2 * p) % 3;             // {1,0,2}
        float lo, hi;
        if (p == 0) {                         // (a[2k], a[2k+1]), zero tail
            lo = 3.0f * h[127 - 6 * k];
            hi = (k < 21) ? 3.0f * h[124 - 6 * k] : 0.0f;
        } else if (k == 0) {                  // head pair (0, a[0])
            lo = 0.0f;
            hi = 3.0f * h[pf + 126];
        } else {                              // (a[2k-1], a[2k])
            lo = 3.0f * h[pf + 129 - 6 * k];
            hi = 3.0f * h[pf + 126 - 6 * k];
        }
        u64 d; PACK_X2(d, lo, hi);
        sh_t[tid] = d;
    }

    const int t0 = blockIdx.x * TPB;
    const int ntloc = min(TPB, n_tiles - t0);

    // ---- load first tile into buffer 0 ----
    {
        const int IB = 1024 * t0 - 21;
        for (int i = tid; i < TQ; i += THREADS) {
            int g0 = IB + 2 * i, g1 = g0 + 1;
            float lo = (g0 >= 0 && g0 < N) ? x[g0] : 0.0f;
            float hi = (g1 >= 0 && g1 < N) ? x[g1] : 0.0f;
            u64 d; PACK_X2(d, lo, hi);
            sh2[0][SP(i)] = d;
        }
    }
    __syncthreads();

    const int wid  = tid >> 5;
    const int lane = tid & 31;
    const int p    = wid % 3;                 // class = j mod 3 (uniform/warp)
    const int u    = (wid / 3) * 32 + lane;   // 0..63 within class
    const u64* __restrict__ T = sh_t + p * NP;

    int cur = 0;
    for (int t = 0; t < ntloc; ++t) {
        const int tt = t0 + t;
        const bool hasnext = (t + 1 < ntloc);

        // prefetch next tile into registers (LDG issued before compute)
        u64 pf3[3];
        if (hasnext) {
            const int IBn = 1024 * (tt + 1) - 21;
            #pragma unroll
            for (int q = 0; q < 3; ++q) {
                int i = tid + q * THREADS;
                float lo = 0.0f, hi = 0.0f;
                if (i < TQ) {
                    int g0 = IBn + 2 * i, g1 = g0 + 1;
                    if (g0 >= 0 && g0 < N) lo = x[g0];
                    if (g1 >= 0 && g1 < N) hi = x[g1];
                }
                PACK_X2(pf3[q], lo, hi);
            }
        }

        // ---- compute tile tt from sh2[cur] ----
        const u64* __restrict__ wb = &sh2[cur][0] + 9 * u;

        u64 wp[29];
        #pragma unroll
        for (int m = 0; m < LOOKAHEAD; ++m)
            wp[m] = wb[m + (m >> 3)];

        u64 acc[RR];
        #pragma unroll
        for (int r = 0; r < RR; ++r) acc[r] = 0ull;

        #pragma unroll
        for (int k = 0; k < NP; ++k) {
            if (k + LOOKAHEAD < 29) {
                const int m = k + LOOKAHEAD;
                wp[m] = wb[m + (m >> 3)];
            }
            const u64 tp = T[k];               // uniform -> LDS.64 broadcast
            #pragma unroll
            for (int r = 0; r < RR; ++r)
                FMA_X2(acc[r], tp, wp[k + r], acc[r]);
        }

        // stage outputs (stride-3 STS: gcd(3,32)=1 -> conflict-free)
        const int q0 = u * RR;
        #pragma unroll
        for (int r = 0; r < RR; ++r) {
            float e, o; UNPACK_X2(e, o, acc[r]);
            sh_out[3 * (q0 + r) + p] = e + o;
        }
        __syncthreads();

        // coalesced global store (float4 fast path; tiles exactly cover n_out)
        const int Jb = tt * NOUT_BLK;
        if (Jb + NOUT_BLK <= n_out) {
            const float4* __restrict__ s4 = (const float4*)sh_out;
            float4* __restrict__ o4 = (float4*)(out + Jb);
            #pragma unroll
            for (int q = 0; q < NOUT_BLK / 4 / THREADS; ++q)   // 2 iterations
                o4[tid + q * THREADS] = s4[tid + q * THREADS];
        } else {
            for (int m = tid; m < NOUT_BLK; m += THREADS) {
                int j = Jb + m;
                if (j < n_out) out[j] = sh_out[m];
            }
        }

        // commit prefetched tile into the other buffer
        if (hasnext) {
            #pragma unroll
            for (int q = 0; q < 3; ++q) {
                int i = tid + q * THREADS;
                if (i < TQ) sh2[cur ^ 1][SP(i)] = pf3[q];
            }
        }
        __syncthreads();
        cur ^= 1;
    }
}

extern "C" void kernel_launch(void* const* d_in, const int* in_sizes, int n_in,
                              void* d_out, int out_size)
{
    const float* x = (const float*)d_in[0];
    const float* h = (const float*)d_in[1];
    float* out = (float*)d_out;

    const int N = in_sizes[0];
    const int n_out = out_size;
    const int n_tiles = (n_out + NOUT_BLK - 1) / NOUT_BLK;       // 2048
    const int grid = (n_tiles + TPB - 1) / TPB;                  // 1024

    poly_resample_kernel<<<grid, THREADS>>>(x, h, out, N, n_out, n_tiles);
}